// round 10
// baseline (speedup 1.0000x reference)
#include <cuda_runtime.h>
#include <math.h>

#define N_ROWS  8000
#define D_DIM   9
#define CHUNK   2000                // rows per chunk
#define NCHUNK  4                   // 4 * 2000 = 8000
#define CH_FLT  (CHUNK * D_DIM)     // 18000 floats per chunk
#define CH_V4   (CH_FLT / 4)        // 4500 float4 per chunk (exact)
#define PF_N    5                   // ceil(4500 / 1024) prefetch regs/thread

// Scratch: device globals (no allocation allowed anywhere)
__device__ float g_df[N_ROWS];     // (f1+b1) - (f2+b2)
__device__ float g_f2[N_ROWS];     // f2 + b2
__device__ float g_wbar[N_ROWS];   // sigmoid(cumsum(s2 - s1))

// ---------------------------------------------------------------------------
// Fused prep: row stats + inclusive scan + sigmoid. ONE block, 1024 threads,
// 4 chunks of 2000 rows. Register prefetch of chunk c+1 overlaps compute of
// chunk c, so only chunk 0's DRAM latency is exposed. Thread t owns rows
// (2t, 2t+1) of each chunk: 2-row serial scan + one block scan per chunk.
// ---------------------------------------------------------------------------
__global__ void __launch_bounds__(1024) k_prep(
    const float* __restrict__ x,
    const float* __restrict__ a1p, const float* __restrict__ c1p,
    const float* __restrict__ a2p, const float* __restrict__ c2p,
    const float* __restrict__ w1,  const float* __restrict__ b1,
    const float* __restrict__ w2,  const float* __restrict__ b2)
{
    __shared__ float s_x[CH_FLT];     // 72 KB (size proven to build/run in R8)
    __shared__ float s_warp[32];

    const int tid  = threadIdx.x;
    const int lane = tid & 31;
    const int wid  = tid >> 5;
    const bool active = (tid < CHUNK / 2);   // 1000 scan lanes

    const float a1 = a1p[0], c1 = c1p[0], a2 = a2p[0], c2 = c2p[0];
    const float inv_a1 = 1.0f / a1, inv_a2 = 1.0f / a2;
    const float b1v = b1[0], b2v = b2[0];

    float w1r[D_DIM], w2r[D_DIM];
#pragma unroll
    for (int d = 0; d < D_DIM; d++) { w1r[d] = w1[d]; w2r[d] = w2[d]; }

    const float4* __restrict__ x4 = (const float4*)x;

    // Prefetch chunk 0
    float4 pf[PF_N];
#pragma unroll
    for (int k = 0; k < PF_N; k++) {
        int v = tid + k * 1024;
        if (v < CH_V4) pf[k] = x4[v];
    }

    float carry = 0.f;

    for (int c = 0; c < NCHUNK; c++) {
        // Commit prefetched chunk c to smem (coalesced float4)
        float4* s4 = (float4*)s_x;
#pragma unroll
        for (int k = 0; k < PF_N; k++) {
            int v = tid + k * 1024;
            if (v < CH_V4) s4[v] = pf[k];
        }
        __syncthreads();

        // Launch chunk c+1 loads now — in flight during compute below
        if (c + 1 < NCHUNK) {
            const float4* src = x4 + (size_t)(c + 1) * CH_V4;
#pragma unroll
            for (int k = 0; k < PF_N; k++) {
                int v = tid + k * 1024;
                if (v < CH_V4) pf[k] = src[v];
            }
        }

        // Row stats for rows 2t, 2t+1 (smem stride-18 reads: <=2-way conflict)
        float e0 = 0.f, e1 = 0.f;  // serial inclusive within thread
        if (active) {
            const float* xr = &s_x[(2 * tid) * D_DIM];
            float s1a = 0.f, s2a = 0.f, f1a = 0.f, f2a = 0.f;
            float s1b = 0.f, s2b = 0.f, f1b = 0.f, f2b = 0.f;
#pragma unroll
            for (int d = 0; d < D_DIM; d++) {
                float xa = xr[d];
                float xb = xr[D_DIM + d];
                float t1a = (xa - c1) * inv_a1, t2a = (xa - c2) * inv_a2;
                float t1b = (xb - c1) * inv_a1, t2b = (xb - c2) * inv_a2;
                s1a = fmaf(t1a, t1a, s1a);  s2a = fmaf(t2a, t2a, s2a);
                s1b = fmaf(t1b, t1b, s1b);  s2b = fmaf(t2b, t2b, s2b);
                f1a = fmaf(xa, w1r[d], f1a); f2a = fmaf(xa, w2r[d], f2a);
                f1b = fmaf(xb, w1r[d], f1b); f2b = fmaf(xb, w2r[d], f2b);
            }
            const int r = c * CHUNK + 2 * tid;
            float f2ba = f2a + b2v;
            float f2bb = f2b + b2v;
            g_f2[r]     = f2ba;
            g_f2[r + 1] = f2bb;
            g_df[r]     = (f1a + b1v) - f2ba;
            g_df[r + 1] = (f1b + b1v) - f2bb;
            e0 = s2a - s1a;
            e1 = e0 + (s2b - s1b);
        }
        float tot = e1;

        // Block scan over thread totals (inactive lanes contribute 0)
        float ws = tot;
#pragma unroll
        for (int off = 1; off < 32; off <<= 1) {
            float t = __shfl_up_sync(0xFFFFFFFFu, ws, off);
            if (lane >= off) ws += t;
        }
        if (lane == 31) s_warp[wid] = ws;
        __syncthreads();
        if (wid == 0) {
            float w = s_warp[lane];
#pragma unroll
            for (int off = 1; off < 32; off <<= 1) {
                float t = __shfl_up_sync(0xFFFFFFFFu, w, off);
                if (lane >= off) w += t;
            }
            s_warp[lane] = w;
        }
        __syncthreads();

        float warp_prefix   = (wid > 0) ? s_warp[wid - 1] : 0.f;
        float thread_prefix = carry + warp_prefix + (ws - tot);

        if (active) {
            const int r = c * CHUNK + 2 * tid;
            float D0 = thread_prefix + e0;
            float D1 = thread_prefix + e1;
            g_wbar[r]     = 1.0f / (1.0f + expf(-D0));
            g_wbar[r + 1] = 1.0f / (1.0f + expf(-D1));
        }
        carry += s_warp[31];
        __syncthreads();   // protect s_warp and s_x before next chunk's commit
    }
}

// ---------------------------------------------------------------------------
// K3: out[i, j] = f2[i] + df[i] * wbar[j]
// Two rows per block (proven best: regs=28, occ=79%), streaming stores.
// UNCHANGED from R9.
// ---------------------------------------------------------------------------
__global__ void __launch_bounds__(256) k3_outer(float* __restrict__ out)
{
    const int rowA = blockIdx.x * 2;
    const int rowB = rowA + 1;

    const float f2A = g_f2[rowA];
    const float dfA = g_df[rowA];
    const float f2B = g_f2[rowB];
    const float dfB = g_df[rowB];

    const float4* __restrict__ wb4 = (const float4*)g_wbar;
    float4* __restrict__ oA = (float4*)(out + (size_t)rowA * N_ROWS);
    float4* __restrict__ oB = (float4*)(out + (size_t)rowB * N_ROWS);

#pragma unroll 4
    for (int j = threadIdx.x; j < N_ROWS / 4; j += 256) {
        float4 w = wb4[j];
        float4 rA, rB;
        rA.x = fmaf(dfA, w.x, f2A); rA.y = fmaf(dfA, w.y, f2A);
        rA.z = fmaf(dfA, w.z, f2A); rA.w = fmaf(dfA, w.w, f2A);
        rB.x = fmaf(dfB, w.x, f2B); rB.y = fmaf(dfB, w.y, f2B);
        rB.z = fmaf(dfB, w.z, f2B); rB.w = fmaf(dfB, w.w, f2B);
        __stcs(&oA[j], rA);
        __stcs(&oB[j], rB);
    }
}

// ---------------------------------------------------------------------------
extern "C" void kernel_launch(void* const* d_in, const int* in_sizes, int n_in,
                              void* d_out, int out_size)
{
    const float* x     = (const float*)d_in[0];
    const float* a1    = (const float*)d_in[1];
    const float* c1    = (const float*)d_in[2];
    const float* a2    = (const float*)d_in[3];
    const float* c2    = (const float*)d_in[4];
    const float* w_fc1 = (const float*)d_in[5];
    const float* b_fc1 = (const float*)d_in[6];
    const float* w_fc2 = (const float*)d_in[7];
    const float* b_fc2 = (const float*)d_in[8];
    float* out = (float*)d_out;

    k_prep<<<1, 1024>>>(x, a1, c1, a2, c2, w_fc1, b_fc1, w_fc2, b_fc2);
    k3_outer<<<N_ROWS / 2, 256>>>(out);
}